// round 16
// baseline (speedup 1.0000x reference)
#include <cuda_runtime.h>
#include <cuda_bf16.h>

#define BATCH 8
#define NBOX 2048
#define MAXDET 100
#define THREADS 512
#define EPT 4                       // sort: elements per thread (blocked)
#define MIN_SIZE 25.0f
#define SCORE_THR 0.001f
#define CIOU 0.23076923f            // 0.3/1.3 : iou>0.3 <=> inter > CIOU*(A+B)
#define FULL 0xffffffffu

typedef unsigned long long u64;
typedef unsigned int u32;

// key: (score bits << 32) | ~idx  -> descending sort == (score desc, idx asc)
__device__ __forceinline__ u64 pack_si(float s, int idx) {
    return ((u64)__float_as_uint(s) << 32) | (u32)(~idx);
}
__device__ __forceinline__ float ciou_area(float4 b) {
    return CIOU * ((b.z - b.x) * (b.w - b.y));
}
__device__ __forceinline__ float inter_of(float4 a, float4 b) {
    float ix = fminf(a.z, b.z) - fmaxf(a.x, b.x);
    float iy = fminf(a.w, b.w) - fmaxf(a.y, b.y);
    return fmaxf(ix, 0.f) * fmaxf(iy, 0.f);
}

extern __shared__ char smem_raw[];
// sbox f4[2048] | skey u64[2048] | pbox f4[100] | pca f[100]
// sdead u32[8] | sacc u32 | smat8 u8[32*4]
#define SMEM_BYTES (32768 + 16384 + 1600 + 400 + 32 + 16 + 128 + 64)

__global__ __launch_bounds__(THREADS, 1)
void nms_kernel(const float* __restrict__ boxes,
                const float* __restrict__ scores,
                float* __restrict__ out,
                int write_mask)
{
    float4* sbox = (float4*)smem_raw;
    u64*    skey = (u64*)(sbox + NBOX);
    float4* pbox = (float4*)(skey + NBOX);
    float*  pca  = (float*)(pbox + MAXDET);
    u32*    sdead = (u32*)(pca + MAXDET);
    u32*    sacc  = sdead + 8;
    unsigned char* smat8 = (unsigned char*)(sacc + 4);
    u32*    smat32 = (u32*)smat8;

    const int img  = blockIdx.x;
    const int tid  = threadIdx.x;
    const int warp = tid >> 5;
    const int lane = tid & 31;
    const int base = tid * EPT;

    // ---- coalesced load, validity filter, keys to shared ----
    const float4* bp = (const float4*)(boxes + (size_t)img * NBOX * 4);
    const float*  sp = scores + (size_t)img * NBOX;
    #pragma unroll
    for (int p = 0; p < NBOX / THREADS; p++) {
        int i = p * THREADS + tid;               // coalesced
        float4 b = bp[i];
        float  s = sp[i];
        float w = b.z - b.x;
        float h = b.w - b.y;
        bool valid = (w >= MIN_SIZE) && (h >= MIN_SIZE) && (s >= SCORE_THR);
        sbox[i] = b;
        skey[i] = valid ? pack_si(s, i) : 0ULL;
    }

    // ---- init output padding: [img,0,0,0,0] rows, mask = 0 ----
    float* outr = out + (size_t)img * MAXDET * 5;
    float* outm = out + (size_t)BATCH * MAXDET * 5 + (size_t)img * MAXDET;
    for (int i = tid; i < MAXDET; i += THREADS) {
        outr[i * 5 + 0] = (float)img;
        outr[i * 5 + 1] = 0.f;
        outr[i * 5 + 2] = 0.f;
        outr[i * 5 + 3] = 0.f;
        outr[i * 5 + 4] = 0.f;
        if (write_mask) outm[i] = 0.f;
    }
    __syncthreads();

    // blocked ownership for the sort
    u64 val[EPT];
    #pragma unroll
    for (int e = 0; e < EPT; e++) val[e] = skey[base + e];

    // ================= bitonic sort (descending) =============================
    // blocked layout: idx = tid*4 + e. bits: [0:1]=e (regs),
    // [2:6]=lane bits (j=4..64 -> shfl), [7:10]=warp bits (j=128..1024 -> smem)

    // presort k=2..4 entirely in registers
    #pragma unroll
    for (int k = 2; k <= 4; k <<= 1) {
        #pragma unroll
        for (int j = k >> 1; j > 0; j >>= 1) {
            #pragma unroll
            for (int e = 0; e < EPT; e++) {
                if ((e & j) == 0) {
                    int f = e | j;
                    bool up = (((base + e) & k) == 0);
                    u64 x = val[e], y = val[f];
                    bool sw = up ? (x < y) : (x > y);
                    if (sw) { val[e] = y; val[f] = x; }
                }
            }
        }
    }

    #pragma unroll 1
    for (int kk = 8; kk <= NBOX; kk <<= 1) {
        const bool dir = ((base & kk) == 0);          // uniform over e (kk>=8)

        // --- shared stages: j in {1024..128} (warp-bit exchanges) ---
        #pragma unroll 1
        for (int j = kk >> 1; j >= 128; j >>= 1) {
            #pragma unroll
            for (int e = 0; e < EPT; e++) skey[base + e] = val[e];
            __syncthreads();
            bool iLow = ((tid & (j >> 2)) == 0);
            int pbase = base ^ j;                     // partner thread's block
            #pragma unroll
            for (int e = 0; e < EPT; e++) {
                u64 o = skey[pbase + e];
                u64 mx = val[e] > o ? val[e] : o;
                u64 mn = val[e] > o ? o : val[e];
                val[e] = (iLow == dir) ? mx : mn;
            }
            __syncthreads();
        }

        // --- shfl stages: j in {64..4} (lane-bit exchanges) ---
        {
            int jhi = (kk >> 1) > 64 ? 64 : (kk >> 1);
            #pragma unroll 1
            for (int j = jhi; j >= 4; j >>= 1) {
                int jl = j >> 2;                      // lane xor mask
                bool iLow = ((tid & jl) == 0);
                #pragma unroll
                for (int e = 0; e < EPT; e++) {
                    u64 o = __shfl_xor_sync(FULL, val[e], jl);
                    u64 mx = val[e] > o ? val[e] : o;
                    u64 mn = val[e] > o ? o : val[e];
                    val[e] = (iLow == dir) ? mx : mn;
                }
            }
        }

        // --- register tail: j = 2..1 ---
        #pragma unroll
        for (int j = 2; j > 0; j >>= 1) {
            #pragma unroll
            for (int e = 0; e < EPT; e++) {
                if ((e & j) == 0) {
                    int f = e | j;
                    u64 x = val[e], y = val[f];
                    bool sw = dir ? (x < y) : (x > y);
                    if (sw) { val[e] = y; val[f] = x; }
                }
            }
        }
    }
    // write sorted keys (rank order) to shared for the batch engine
    #pragma unroll
    for (int e = 0; e < EPT; e++) skey[base + e] = val[e];
    __syncthreads();

    // ================= lazy greedy: batch-verified walk in rank order ========
    int npicks = 0;
    int rb = 0;
    while (rb < NBOX && npicks < MAXDET) {
        // every warp stages the same 32 candidates (broadcast LDS)
        u64 kkey = skey[rb + lane];
        if (__shfl_sync(FULL, kkey, 0) == 0ULL) break;   // rank rb invalid => done

        int cidx = (int)(~(u32)kkey) & (NBOX - 1);
        float4 myb = sbox[cidx];               // candidate = lane (all warps)
        float  mya = ciou_area(myb);
        u32 vmask = __ballot_sync(FULL, kkey != 0ULL);   // identical per warp

        if (warp < 4) {
            // (b) 32x32 pairwise overlap: partner boxes via shfl from lane c
            u32 bits8 = 0;
            #pragma unroll
            for (int q = 0; q < 8; q++) {
                int c = warp * 8 + q;
                float4 ob;
                ob.x = __shfl_sync(FULL, myb.x, c);
                ob.y = __shfl_sync(FULL, myb.y, c);
                ob.z = __shfl_sync(FULL, myb.z, c);
                ob.w = __shfl_sync(FULL, myb.w, c);
                float oa = __shfl_sync(FULL, mya, c);
                bool ov = inter_of(myb, ob) > mya + oa;
                bits8 |= (ov ? 1u : 0u) << q;
            }
            smat8[lane * 4 + warp] = (unsigned char)bits8;
        } else if (warp < 12) {
            // (a) candidate vs existing picks (picks strided over warps 4-11)
            bool dead = false;
            for (int j = warp - 4; j < npicks; j += 8) {
                float4 pb = pbox[j];
                dead |= inter_of(pb, myb) > pca[j] + mya;
            }
            u32 bal = __ballot_sync(FULL, dead);
            if (lane == 0) sdead[warp - 4] = bal;
        }
        __syncthreads();

        // (c)+(d): warp 0 only — walk + append picks + write output
        if (warp == 0) {
            u32 deadP = (sdead[0] | sdead[1]) | (sdead[2] | sdead[3]);
            deadP |= (sdead[4] | sdead[5]) | (sdead[6] | sdead[7]);
            u32 elig  = vmask & ~deadP;

            u32 rows[32];
            #pragma unroll
            for (int j = 0; j < 32; j++) rows[j] = smat32[j];
            u32 acc = 0;
            #pragma unroll
            for (int j = 0; j < 32; j++) {
                bool take = ((elig >> j) & 1u) && ((acc & rows[j]) == 0u);
                acc |= (take ? 1u : 0u) << j;
            }
            if (lane == 0) *sacc = acc;

            if ((acc >> lane) & 1u) {          // lane == candidate
                int slot = npicks + __popc(acc & ((1u << lane) - 1u));
                if (slot < MAXDET) {
                    pbox[slot] = myb;
                    pca[slot]  = mya;
                    float* row = outr + slot * 5;
                    row[1] = myb.x; row[2] = myb.y; row[3] = myb.z; row[4] = myb.w;
                    if (write_mask) outm[slot] = 1.f;
                }
            }
        }
        __syncthreads();                       // pbox/pca/sacc visible to all

        npicks = min(npicks + __popc(*sacc), MAXDET);
        rb += 32;
    }
}

extern "C" void kernel_launch(void* const* d_in, const int* in_sizes, int n_in,
                              void* d_out, int out_size) {
    const float* boxes  = (const float*)d_in[0];   // [8,2048,4] f32
    const float* scores = (const float*)d_in[1];   // [8,2048]   f32
    float* out = (float*)d_out;
    int write_mask = (out_size >= BATCH * MAXDET * 5 + BATCH * MAXDET) ? 1 : 0;

    static int attr_done = 0;
    if (!attr_done) {
        cudaFuncSetAttribute(nms_kernel,
                             cudaFuncAttributeMaxDynamicSharedMemorySize,
                             SMEM_BYTES);
        attr_done = 1;
    }
    nms_kernel<<<BATCH, THREADS, SMEM_BYTES>>>(boxes, scores, out, write_mask);
}